// round 1
// baseline (speedup 1.0000x reference)
#include <cuda_runtime.h>
#include <math.h>

#define BB   4
#define TT   32768
#define BT   (BB*TT)           // 131072 points
#define QQ   8192
#define HH   128
#define RR   64
#define RR2  4096
#define CDIM 512

// ---------------- scratch (static device memory; no allocations) ----------------
__device__ float    g_X  [BT*256];            // block input (concat buffer)  134 MB
__device__ float    g_H  [BT*128];            // hidden                        67 MB
__device__ float    g_NET[BT*128];            // block output                  67 MB
__device__ float    g_C  [BT*CDIM];           // fc_c output                  256 MB
__device__ unsigned g_MAX[3*BB*RR2*128];      // per-plane max pool            25 MB
__device__ float    g_FEA[3*BB*RR2*CDIM];     // per-plane mean feat          100 MB
__device__ float    g_CNT[3*BB*RR2];          // per-plane counts
__device__ int      g_IDX[3*BT];              // per-plane cell index

// ---------------- helpers ----------------
__device__ __forceinline__ unsigned f2o(float f) {
    unsigned b = __float_as_uint(f);
    return (b & 0x80000000u) ? ~b : (b | 0x80000000u);
}
__device__ __forceinline__ float o2f(unsigned o) {
    return __uint_as_float((o & 0x80000000u) ? (o ^ 0x80000000u) : ~o);
}
__device__ __forceinline__ float nrmc(float v) {
    v = v * (1.0f / 1.1f) + 0.5f;
    return fminf(fmaxf(v, 0.0f), 1.0f - 1e-6f);
}

// ---------------- index computation ----------------
__global__ void k_index(const float* __restrict__ p) {
    int t = blockIdx.x * 256 + threadIdx.x;
    if (t >= BT) return;
    float x = p[t*3+0], y = p[t*3+1], z = p[t*3+2];
    int gx, gy;
    gx = (int)floorf(nrmc(x) * RR); gy = (int)floorf(nrmc(z) * RR);
    g_IDX[0*BT + t] = gx + RR*gy;                       // xz
    gx = (int)floorf(nrmc(x) * RR); gy = (int)floorf(nrmc(y) * RR);
    g_IDX[1*BT + t] = gx + RR*gy;                       // xy
    gx = (int)floorf(nrmc(y) * RR); gy = (int)floorf(nrmc(z) * RR);
    g_IDX[2*BT + t] = gx + RR*gy;                       // yz
}

// ---------------- fc_pos: X0 = p @ W(3,256) + b ----------------
__global__ void k_pos(const float* __restrict__ p, const float* __restrict__ w,
                      const float* __restrict__ b) {
    int gi = blockIdx.x * 256 + threadIdx.x;   // BT*256 threads
    int t = gi >> 8, j = gi & 255;
    float p0 = p[t*3+0], p1 = p[t*3+1], p2 = p[t*3+2];
    g_X[gi] = p0 * w[j] + p1 * w[256 + j] + p2 * w[512 + j] + b[j];
}

// ---------------- generic tiled SGEMM: C = [C +] act(A) @ W [+ bias] ----------------
// A: (BT, K) row-major, W: (K, Nout) row-major, C: (BT, Nout)
template<int K, bool RELU, bool ACCUM, bool BIAS>
__global__ void k_gemm(const float* __restrict__ A, const float* __restrict__ W,
                       const float* __restrict__ bias, float* __restrict__ Cm, int Nout) {
    __shared__ float As[16][68];  // [k][m]
    __shared__ float Ws[16][68];  // [k][n]
    int tid  = threadIdx.x;
    int row0 = blockIdx.y * 64;
    int col0 = blockIdx.x * 64;
    int ty = tid >> 4, tx = tid & 15;

    int ar = tid >> 2;          // 0..63 : A row within tile
    int ak = (tid & 3) * 4;     // 0..12 : A k offset
    int wr = tid >> 4;          // 0..15 : W k row
    int wc = (tid & 15) * 4;    // 0..60 : W col offset

    float acc[4][4];
#pragma unroll
    for (int i = 0; i < 4; i++)
#pragma unroll
        for (int j = 0; j < 4; j++) acc[i][j] = 0.0f;

    for (int k0 = 0; k0 < K; k0 += 16) {
        float4 av = *(const float4*)&A[(row0 + ar) * K + k0 + ak];
        if (RELU) {
            av.x = fmaxf(av.x, 0.0f); av.y = fmaxf(av.y, 0.0f);
            av.z = fmaxf(av.z, 0.0f); av.w = fmaxf(av.w, 0.0f);
        }
        As[ak + 0][ar] = av.x; As[ak + 1][ar] = av.y;
        As[ak + 2][ar] = av.z; As[ak + 3][ar] = av.w;
        *(float4*)&Ws[wr][wc] = *(const float4*)&W[(k0 + wr) * Nout + col0 + wc];
        __syncthreads();
#pragma unroll
        for (int kk = 0; kk < 16; kk++) {
            float a[4], b[4];
#pragma unroll
            for (int i = 0; i < 4; i++) a[i] = As[kk][ty * 4 + i];
#pragma unroll
            for (int j = 0; j < 4; j++) b[j] = Ws[kk][tx * 4 + j];
#pragma unroll
            for (int i = 0; i < 4; i++)
#pragma unroll
                for (int j = 0; j < 4; j++) acc[i][j] += a[i] * b[j];
        }
        __syncthreads();
    }

#pragma unroll
    for (int i = 0; i < 4; i++) {
        int row = row0 + ty * 4 + i;
#pragma unroll
        for (int j = 0; j < 4; j++) {
            int col = col0 + tx * 4 + j;
            float v = acc[i][j];
            if (BIAS)  v += bias[col];
            int o = row * Nout + col;
            if (ACCUM) v += Cm[o];
            Cm[o] = v;
        }
    }
}

// ---------------- zeroing ----------------
__global__ void k_zero_u(unsigned* ptr, int n) {
    for (int i = blockIdx.x * 256 + threadIdx.x; i < n; i += gridDim.x * 256) ptr[i] = 0u;
}
__global__ void k_zero_f(float* ptr, int n) {
    for (int i = blockIdx.x * 256 + threadIdx.x; i < n; i += gridDim.x * 256) ptr[i] = 0.0f;
}

// ---------------- scatter max over 3 planes ----------------
__global__ void k_scatter_max() {
    int gi = blockIdx.x * 256 + threadIdx.x;   // BT*128 threads
    int t = gi >> 7, ch = gi & 127;
    int b = t >> 15;
    unsigned o = f2o(g_NET[gi]);
#pragma unroll
    for (int pl = 0; pl < 3; pl++) {
        int cell = g_IDX[pl * BT + t];
        atomicMax(&g_MAX[((pl * BB + b) * RR2 + cell) * 128 + ch], o);
    }
}

// ---------------- gather pooled + build concat input ----------------
__global__ void k_gather() {
    int gi = blockIdx.x * 256 + threadIdx.x;   // BT*128 threads
    int t = gi >> 7, ch = gi & 127;
    int b = t >> 15;
    g_X[t * 256 + ch] = g_NET[gi];
    float s = 0.0f;
#pragma unroll
    for (int pl = 0; pl < 3; pl++) {
        int cell = g_IDX[pl * BT + t];
        s += o2f(g_MAX[((pl * BB + b) * RR2 + cell) * 128 + ch]);
    }
    g_X[t * 256 + 128 + ch] = s;
}

// ---------------- scatter mean ----------------
__global__ void k_count() {
    int t = blockIdx.x * 256 + threadIdx.x;
    if (t >= BT) return;
    int b = t >> 15;
#pragma unroll
    for (int pl = 0; pl < 3; pl++)
        atomicAdd(&g_CNT[(pl * BB + b) * RR2 + g_IDX[pl * BT + t]], 1.0f);
}
__global__ void k_scatter_add() {
    int gi = blockIdx.x * 256 + threadIdx.x;   // BT*512 threads
    int t = gi >> 9, ch = gi & 511;
    int b = t >> 15;
    float v = g_C[gi];
#pragma unroll
    for (int pl = 0; pl < 3; pl++) {
        int cell = g_IDX[pl * BT + t];
        atomicAdd(&g_FEA[((pl * BB + b) * RR2 + cell) * CDIM + ch], v);
    }
}
__global__ void k_div() {
    int gi = blockIdx.x * 256 + threadIdx.x;   // 3*BB*RR2*512 threads
    int cell = gi >> 9;
    g_FEA[gi] = g_FEA[gi] / fmaxf(g_CNT[cell], 1.0f);
}

// ---------------- bilinear sample + sum over planes ----------------
__device__ __forceinline__ float samp_plane(int pl, float u, float v, int b, int ch) {
    float nu = nrmc(u), nv = nrmc(v);
    float gx = nu * (RR - 1), gy = nv * (RR - 1);
    float x0f = floorf(gx), y0f = floorf(gy);
    float wx = gx - x0f, wy = gy - y0f;
    int x0 = min(max((int)x0f, 0), RR - 1);
    int x1 = min(x0 + 1, RR - 1);
    int y0 = min(max((int)y0f, 0), RR - 1);
    int y1 = min(y0 + 1, RR - 1);
    const float* f = g_FEA + (size_t)((pl * BB + b) * RR2) * CDIM;
    float f00 = f[(y0 * RR + x0) * CDIM + ch];
    float f01 = f[(y0 * RR + x1) * CDIM + ch];
    float f10 = f[(y1 * RR + x0) * CDIM + ch];
    float f11 = f[(y1 * RR + x1) * CDIM + ch];
    float top = f00 * (1.0f - wx) + f01 * wx;
    float bot = f10 * (1.0f - wx) + f11 * wx;
    return top * (1.0f - wy) + bot * wy;
}

__global__ void k_sample(const float* __restrict__ query, float* __restrict__ out) {
    int gi = blockIdx.x * 256 + threadIdx.x;   // BB*QQ*512 threads
    int ch = gi & 511;
    int q  = gi >> 9;       // 0 .. BB*QQ-1
    int b  = q >> 13;       // QQ = 8192
    float qx = query[q*3+0], qy = query[q*3+1], qz = query[q*3+2];
    float acc = 0.0f;
    acc += samp_plane(0, qx, qz, b, ch);   // xz
    acc += samp_plane(1, qx, qy, b, ch);   // xy
    acc += samp_plane(2, qy, qz, b, ch);   // yz
    out[gi] = acc;
}

// ---------------- launch ----------------
extern "C" void kernel_launch(void* const* d_in, const int* in_sizes, int n_in,
                              void* d_out, int out_size) {
    const float* p        = (const float*)d_in[0];
    const float* query    = (const float*)d_in[1];
    const float* fc_pos_w = (const float*)d_in[2];
    const float* fc_pos_b = (const float*)d_in[3];
    const float* blk_w0   = (const float*)d_in[4];
    const float* blk_b0   = (const float*)d_in[5];
    const float* blk_w1   = (const float*)d_in[6];
    const float* blk_b1   = (const float*)d_in[7];
    const float* blk_ws   = (const float*)d_in[8];
    const float* fc_c_w   = (const float*)d_in[9];
    const float* fc_c_b   = (const float*)d_in[10];
    float* out = (float*)d_out;

    float *X, *H, *NET, *Cb, *FEA, *CNT;
    unsigned* MAXB;
    cudaGetSymbolAddress((void**)&X,    g_X);
    cudaGetSymbolAddress((void**)&H,    g_H);
    cudaGetSymbolAddress((void**)&NET,  g_NET);
    cudaGetSymbolAddress((void**)&Cb,   g_C);
    cudaGetSymbolAddress((void**)&FEA,  g_FEA);
    cudaGetSymbolAddress((void**)&CNT,  g_CNT);
    cudaGetSymbolAddress((void**)&MAXB, g_MAX);

    k_index<<<BT/256, 256>>>(p);
    k_pos<<<BT, 256>>>(p, fc_pos_w, fc_pos_b);

    dim3 g128(128/64, BT/64);   // (2, 2048)
    dim3 g512(512/64, BT/64);   // (8, 2048)

    for (int i = 0; i < 5; i++) {
        if (i > 0) {
            k_zero_u<<<2048, 256>>>(MAXB, 3*BB*RR2*128);
            k_scatter_max<<<BT*128/256, 256>>>();
            k_gather<<<BT*128/256, 256>>>();
        }
        const float* w0 = blk_w0 + i*256*128;
        const float* b0 = blk_b0 + i*128;
        const float* w1 = blk_w1 + i*128*128;
        const float* b1 = blk_b1 + i*128;
        const float* ws = blk_ws + i*256*128;
        // H = relu(X) @ w0 + b0
        k_gemm<256, true,  false, true ><<<g128, 256>>>(X, w0, b0, H, 128);
        // NET = X @ ws
        k_gemm<256, false, false, false><<<g128, 256>>>(X, ws, nullptr, NET, 128);
        // NET += relu(H) @ w1 + b1
        k_gemm<128, true,  true,  true ><<<g128, 256>>>(H, w1, b1, NET, 128);
    }

    // c = NET @ fc_c_w + fc_c_b
    k_gemm<128, false, false, true><<<g512, 256>>>(NET, fc_c_w, fc_c_b, Cb, 512);

    // scatter mean into plane grids
    k_zero_f<<<4096, 256>>>(FEA, 3*BB*RR2*CDIM);
    k_zero_f<<<48,   256>>>(CNT, 3*BB*RR2);
    k_count<<<BT/256, 256>>>();
    k_scatter_add<<<BT*512/256, 256>>>();
    k_div<<<3*BB*RR2*CDIM/256, 256>>>();

    // bilinear sample queries
    k_sample<<<BB*QQ*512/256, 256>>>(query, out);
}

// round 2
// speedup vs baseline: 1.7466x; 1.7466x over previous
#include <cuda_runtime.h>
#include <math.h>
#include <stdint.h>

#define BB   4
#define TT   32768
#define BT   (BB*TT)           // 131072 points
#define QQ   8192
#define HH   128
#define RR   64
#define RR2  4096
#define CDIM 512

// ---------------- scratch (static device memory; no allocations) ----------------
__device__ float    g_X  [BT*256];            // block input (concat buffer)
__device__ float    g_H  [BT*128];            // hidden
__device__ float    g_NET[BT*128];            // block output
__device__ float    g_C  [BT*CDIM];           // fc_c output
__device__ unsigned g_MAX[3*BB*RR2*128];      // per-plane max pool
__device__ float    g_FEA[3*BB*RR2*CDIM];     // per-plane mean feat
__device__ float    g_CNT[3*BB*RR2];          // per-plane counts
__device__ int      g_IDX[3*BT];              // per-plane cell index

// ---------------- helpers ----------------
__device__ __forceinline__ unsigned f2o(float f) {
    unsigned b = __float_as_uint(f);
    return (b & 0x80000000u) ? ~b : (b | 0x80000000u);
}
__device__ __forceinline__ float o2f(unsigned o) {
    return __uint_as_float((o & 0x80000000u) ? (o ^ 0x80000000u) : ~o);
}
__device__ __forceinline__ float nrmc(float v) {
    v = v * (1.0f / 1.1f) + 0.5f;
    return fminf(fmaxf(v, 0.0f), 1.0f - 1e-6f);
}
__device__ __forceinline__ uint32_t to_tf32(float x) {
    uint32_t u;
    asm("cvt.rna.tf32.f32 %0, %1;" : "=r"(u) : "f"(x));
    return u;
}
__device__ __forceinline__ void mma_tf32(float c[4], const uint32_t a[4], const uint32_t b[2]) {
    asm volatile(
        "mma.sync.aligned.m16n8k8.row.col.f32.tf32.tf32.f32 "
        "{%0,%1,%2,%3}, {%4,%5,%6,%7}, {%8,%9}, {%0,%1,%2,%3};"
        : "+f"(c[0]), "+f"(c[1]), "+f"(c[2]), "+f"(c[3])
        : "r"(a[0]), "r"(a[1]), "r"(a[2]), "r"(a[3]), "r"(b[0]), "r"(b[1]));
}

// ---------------- index computation + counts ----------------
__global__ void k_index(const float* __restrict__ p) {
    int t = blockIdx.x * 256 + threadIdx.x;
    if (t >= BT) return;
    float x = p[t*3+0], y = p[t*3+1], z = p[t*3+2];
    int b = t >> 15;
    int gx, gy, cell;
    gx = (int)floorf(nrmc(x) * RR); gy = (int)floorf(nrmc(z) * RR);
    cell = gx + RR*gy; g_IDX[0*BT + t] = cell;
    atomicAdd(&g_CNT[(0*BB + b)*RR2 + cell], 1.0f);
    gx = (int)floorf(nrmc(x) * RR); gy = (int)floorf(nrmc(y) * RR);
    cell = gx + RR*gy; g_IDX[1*BT + t] = cell;
    atomicAdd(&g_CNT[(1*BB + b)*RR2 + cell], 1.0f);
    gx = (int)floorf(nrmc(y) * RR); gy = (int)floorf(nrmc(z) * RR);
    cell = gx + RR*gy; g_IDX[2*BT + t] = cell;
    atomicAdd(&g_CNT[(2*BB + b)*RR2 + cell], 1.0f);
}

// ---------------- fc_pos: X0 = p @ W(3,256) + b ----------------
__global__ void k_pos(const float* __restrict__ p, const float* __restrict__ w,
                      const float* __restrict__ b) {
    int gi = blockIdx.x * 256 + threadIdx.x;   // BT*256 threads
    int t = gi >> 8, j = gi & 255;
    float p0 = p[t*3+0], p1 = p[t*3+1], p2 = p[t*3+2];
    g_X[gi] = p0 * w[j] + p1 * w[256 + j] + p2 * w[512 + j] + b[j];
}

// ---------------- TF32 tensor-core GEMM ----------------
// C(BT x Nout) = [C +] act(A(BT x K)) @ W(K x Nout) [+ bias]
// block tile 128x128, 4 warps (warp tile 64x64), k-chunk 32.
template<int K, bool RELU, bool ACCUM, bool BIAS>
__global__ void __launch_bounds__(128) k_tgemm(const float* __restrict__ A,
                                               const float* __restrict__ W,
                                               const float* __restrict__ bias,
                                               float* __restrict__ Cm, int Nout) {
    // As[m][kperm]: k within each group of 8 permuted so (tig, tig+4) are adjacent.
    __shared__ float As[128][40];
    __shared__ float Bs[32][136];   // Bs[k][n]

    int tid  = threadIdx.x;
    int wid  = tid >> 5, lane = tid & 31;
    int gid  = lane >> 2, tig = lane & 3;
    int wm   = (wid >> 1) * 64;     // warp row offset within block tile
    int wn   = (wid & 1) * 64;      // warp col offset
    int row0 = blockIdx.y * 128;
    int col0 = blockIdx.x * 128;

    float acc[4][8][4];
#pragma unroll
    for (int mf = 0; mf < 4; mf++)
#pragma unroll
        for (int nf = 0; nf < 8; nf++)
#pragma unroll
            for (int i = 0; i < 4; i++) acc[mf][nf][i] = 0.0f;

    for (int k0 = 0; k0 < K; k0 += 32) {
        // --- load A tile 128x32 (8 float4 per thread), permuted k, tf32-rounded ---
#pragma unroll
        for (int i = 0; i < 8; i++) {
            int chunk = i * 128 + tid;
            int r  = chunk >> 3;
            int c4 = chunk & 7;
            float4 v = *(const float4*)&A[(row0 + r) * K + k0 + c4 * 4];
            if (RELU) {
                v.x = fmaxf(v.x, 0.0f); v.y = fmaxf(v.y, 0.0f);
                v.z = fmaxf(v.z, 0.0f); v.w = fmaxf(v.w, 0.0f);
            }
            int g    = c4 >> 1;
            int base = g * 8 + (c4 & 1);
            As[r][base + 0] = __uint_as_float(to_tf32(v.x));
            As[r][base + 2] = __uint_as_float(to_tf32(v.y));
            As[r][base + 4] = __uint_as_float(to_tf32(v.z));
            As[r][base + 6] = __uint_as_float(to_tf32(v.w));
        }
        // --- load B tile 32x128 (8 float4 per thread) ---
#pragma unroll
        for (int i = 0; i < 8; i++) {
            int chunk = i * 128 + tid;
            int kr  = chunk >> 5;
            int nc4 = chunk & 31;
            float4 v = *(const float4*)&W[(k0 + kr) * Nout + col0 + nc4 * 4];
            v.x = __uint_as_float(to_tf32(v.x));
            v.y = __uint_as_float(to_tf32(v.y));
            v.z = __uint_as_float(to_tf32(v.z));
            v.w = __uint_as_float(to_tf32(v.w));
            *(float4*)&Bs[kr][nc4 * 4] = v;
        }
        __syncthreads();

#pragma unroll
        for (int kk = 0; kk < 32; kk += 8) {
            uint32_t af[4][4];
#pragma unroll
            for (int mf = 0; mf < 4; mf++) {
                int r = wm + mf * 16;
                float2 lo = *(float2*)&As[r + gid    ][kk + tig * 2];
                float2 hi = *(float2*)&As[r + gid + 8][kk + tig * 2];
                af[mf][0] = __float_as_uint(lo.x);
                af[mf][2] = __float_as_uint(lo.y);
                af[mf][1] = __float_as_uint(hi.x);
                af[mf][3] = __float_as_uint(hi.y);
            }
            uint32_t bf[8][2];
#pragma unroll
            for (int nf = 0; nf < 8; nf++) {
                bf[nf][0] = __float_as_uint(Bs[kk + tig    ][wn + nf * 8 + gid]);
                bf[nf][1] = __float_as_uint(Bs[kk + tig + 4][wn + nf * 8 + gid]);
            }
#pragma unroll
            for (int mf = 0; mf < 4; mf++)
#pragma unroll
                for (int nf = 0; nf < 8; nf++)
                    mma_tf32(acc[mf][nf], af[mf], bf[nf]);
        }
        __syncthreads();
    }

    // --- epilogue ---
#pragma unroll
    for (int mf = 0; mf < 4; mf++) {
        int r0 = row0 + wm + mf * 16 + gid;
#pragma unroll
        for (int nf = 0; nf < 8; nf++) {
            int c = col0 + wn + nf * 8 + 2 * tig;
            float v0 = acc[mf][nf][0], v1 = acc[mf][nf][1];
            float v2 = acc[mf][nf][2], v3 = acc[mf][nf][3];
            if (BIAS) {
                float b0 = bias[c], b1 = bias[c + 1];
                v0 += b0; v1 += b1; v2 += b0; v3 += b1;
            }
            float2* p0 = (float2*)&Cm[(size_t)r0 * Nout + c];
            float2* p1 = (float2*)&Cm[(size_t)(r0 + 8) * Nout + c];
            if (ACCUM) {
                float2 o0 = *p0; v0 += o0.x; v1 += o0.y;
                float2 o1 = *p1; v2 += o1.x; v3 += o1.y;
            }
            float2 s0; s0.x = v0; s0.y = v1; *p0 = s0;
            float2 s1; s1.x = v2; s1.y = v3; *p1 = s1;
        }
    }
}

// ---------------- zeroing ----------------
__global__ void k_zero_u(unsigned* ptr, int n) {
    for (int i = blockIdx.x * 256 + threadIdx.x; i < n; i += gridDim.x * 256) ptr[i] = 0u;
}
__global__ void k_zero_f(float* ptr, int n) {
    for (int i = blockIdx.x * 256 + threadIdx.x; i < n; i += gridDim.x * 256) ptr[i] = 0.0f;
}

// ---------------- scatter max over 3 planes ----------------
__global__ void k_scatter_max() {
    int gi = blockIdx.x * 256 + threadIdx.x;   // BT*128 threads
    int t = gi >> 7, ch = gi & 127;
    int b = t >> 15;
    unsigned o = f2o(g_NET[gi]);
#pragma unroll
    for (int pl = 0; pl < 3; pl++) {
        int cell = g_IDX[pl * BT + t];
        atomicMax(&g_MAX[((pl * BB + b) * RR2 + cell) * 128 + ch], o);
    }
}

// ---------------- gather pooled + build concat input ----------------
__global__ void k_gather() {
    int gi = blockIdx.x * 256 + threadIdx.x;   // BT*128 threads
    int t = gi >> 7, ch = gi & 127;
    int b = t >> 15;
    g_X[t * 256 + ch] = g_NET[gi];
    float s = 0.0f;
#pragma unroll
    for (int pl = 0; pl < 3; pl++) {
        int cell = g_IDX[pl * BT + t];
        s += o2f(g_MAX[((pl * BB + b) * RR2 + cell) * 128 + ch]);
    }
    g_X[t * 256 + 128 + ch] = s;
}

// ---------------- scatter mean ----------------
__global__ void k_scatter_add() {
    int gi = blockIdx.x * 256 + threadIdx.x;   // BT*512 threads
    int t = gi >> 9, ch = gi & 511;
    int b = t >> 15;
    float v = g_C[gi];
#pragma unroll
    for (int pl = 0; pl < 3; pl++) {
        int cell = g_IDX[pl * BT + t];
        atomicAdd(&g_FEA[((pl * BB + b) * RR2 + cell) * CDIM + ch], v);
    }
}
__global__ void k_div() {
    int gi = blockIdx.x * 256 + threadIdx.x;   // 3*BB*RR2*512 threads
    int cell = gi >> 9;
    g_FEA[gi] = g_FEA[gi] / fmaxf(g_CNT[cell], 1.0f);
}

// ---------------- bilinear sample + sum over planes ----------------
__device__ __forceinline__ float samp_plane(int pl, float u, float v, int b, int ch) {
    float nu = nrmc(u), nv = nrmc(v);
    float gx = nu * (RR - 1), gy = nv * (RR - 1);
    float x0f = floorf(gx), y0f = floorf(gy);
    float wx = gx - x0f, wy = gy - y0f;
    int x0 = min(max((int)x0f, 0), RR - 1);
    int x1 = min(x0 + 1, RR - 1);
    int y0 = min(max((int)y0f, 0), RR - 1);
    int y1 = min(y0 + 1, RR - 1);
    const float* f = g_FEA + (size_t)((pl * BB + b) * RR2) * CDIM;
    float f00 = f[(y0 * RR + x0) * CDIM + ch];
    float f01 = f[(y0 * RR + x1) * CDIM + ch];
    float f10 = f[(y1 * RR + x0) * CDIM + ch];
    float f11 = f[(y1 * RR + x1) * CDIM + ch];
    float top = f00 * (1.0f - wx) + f01 * wx;
    float bot = f10 * (1.0f - wx) + f11 * wx;
    return top * (1.0f - wy) + bot * wy;
}

__global__ void k_sample(const float* __restrict__ query, float* __restrict__ out) {
    int gi = blockIdx.x * 256 + threadIdx.x;   // BB*QQ*512 threads
    int ch = gi & 511;
    int q  = gi >> 9;       // 0 .. BB*QQ-1
    int b  = q >> 13;       // QQ = 8192
    float qx = query[q*3+0], qy = query[q*3+1], qz = query[q*3+2];
    float acc = 0.0f;
    acc += samp_plane(0, qx, qz, b, ch);   // xz
    acc += samp_plane(1, qx, qy, b, ch);   // xy
    acc += samp_plane(2, qy, qz, b, ch);   // yz
    out[gi] = acc;
}

// ---------------- launch ----------------
extern "C" void kernel_launch(void* const* d_in, const int* in_sizes, int n_in,
                              void* d_out, int out_size) {
    const float* p        = (const float*)d_in[0];
    const float* query    = (const float*)d_in[1];
    const float* fc_pos_w = (const float*)d_in[2];
    const float* fc_pos_b = (const float*)d_in[3];
    const float* blk_w0   = (const float*)d_in[4];
    const float* blk_b0   = (const float*)d_in[5];
    const float* blk_w1   = (const float*)d_in[6];
    const float* blk_b1   = (const float*)d_in[7];
    const float* blk_ws   = (const float*)d_in[8];
    const float* fc_c_w   = (const float*)d_in[9];
    const float* fc_c_b   = (const float*)d_in[10];
    float* out = (float*)d_out;

    float *X, *H, *NET, *Cb, *FEA, *CNT;
    unsigned* MAXB;
    cudaGetSymbolAddress((void**)&X,    g_X);
    cudaGetSymbolAddress((void**)&H,    g_H);
    cudaGetSymbolAddress((void**)&NET,  g_NET);
    cudaGetSymbolAddress((void**)&Cb,   g_C);
    cudaGetSymbolAddress((void**)&FEA,  g_FEA);
    cudaGetSymbolAddress((void**)&CNT,  g_CNT);
    cudaGetSymbolAddress((void**)&MAXB, g_MAX);

    k_zero_f<<<48, 256>>>(CNT, 3*BB*RR2);
    k_index<<<BT/256, 256>>>(p);
    k_pos<<<BT, 256>>>(p, fc_pos_w, fc_pos_b);

    dim3 g128(1, BT/128);   // Nout=128
    dim3 g512(4, BT/128);   // Nout=512

    for (int i = 0; i < 5; i++) {
        if (i > 0) {
            k_zero_u<<<2048, 256>>>(MAXB, 3*BB*RR2*128);
            k_scatter_max<<<BT*128/256, 256>>>();
            k_gather<<<BT*128/256, 256>>>();
        }
        const float* w0 = blk_w0 + i*256*128;
        const float* b0 = blk_b0 + i*128;
        const float* w1 = blk_w1 + i*128*128;
        const float* b1 = blk_b1 + i*128;
        const float* ws = blk_ws + i*256*128;
        // H = relu(X) @ w0 + b0
        k_tgemm<256, true,  false, true ><<<g128, 128>>>(X, w0, b0, H, 128);
        // NET = X @ ws
        k_tgemm<256, false, false, false><<<g128, 128>>>(X, ws, nullptr, NET, 128);
        // NET += relu(H) @ w1 + b1
        k_tgemm<128, true,  true,  true ><<<g128, 128>>>(H, w1, b1, NET, 128);
    }

    // c = NET @ fc_c_w + fc_c_b
    k_tgemm<128, false, false, true><<<g512, 128>>>(NET, fc_c_w, fc_c_b, Cb, 512);

    // scatter mean into plane grids
    k_zero_f<<<4096, 256>>>(FEA, 3*BB*RR2*CDIM);
    k_scatter_add<<<BT*512/256, 256>>>();
    k_div<<<3*BB*RR2*CDIM/256, 256>>>();

    // bilinear sample queries
    k_sample<<<BB*QQ*512/256, 256>>>(query, out);
}

// round 3
// speedup vs baseline: 2.1278x; 1.2182x over previous
#include <cuda_runtime.h>
#include <math.h>
#include <stdint.h>

#define BB   4
#define TT   32768
#define BT   (BB*TT)           // 131072 points
#define QQ   8192
#define HH   128
#define RR   64
#define RR2  4096
#define CDIM 512

// ---------------- scratch (static device memory; no allocations) ----------------
__device__ float    g_X  [BT*256];            // [NET | pooled] concat buffer
__device__ float    g_H  [BT*128];            // hidden
__device__ float    g_NT [BT*128];            // shortcut temp
__device__ float    g_C  [BT*CDIM];           // fc_c output
__device__ unsigned g_MAX[3*BB*RR2*128];      // per-plane max pool
__device__ float    g_FEA[3*BB*RR2*CDIM];     // per-plane mean feat
__device__ float    g_CNT[3*BB*RR2];          // per-plane counts
__device__ int      g_IDX[3*BT];              // per-plane cell index

// ---------------- helpers ----------------
__device__ __forceinline__ unsigned f2o(float f) {
    unsigned b = __float_as_uint(f);
    return (b & 0x80000000u) ? ~b : (b | 0x80000000u);
}
__device__ __forceinline__ float o2f(unsigned o) {
    return __uint_as_float((o & 0x80000000u) ? (o ^ 0x80000000u) : ~o);
}
__device__ __forceinline__ float nrmc(float v) {
    v = v * (1.0f / 1.1f) + 0.5f;
    return fminf(fmaxf(v, 0.0f), 1.0f - 1e-6f);
}
__device__ __forceinline__ uint32_t to_tf32(float x) {
    uint32_t u;
    asm("cvt.rna.tf32.f32 %0, %1;" : "=r"(u) : "f"(x));
    return u;
}
__device__ __forceinline__ void mma_tf32(float c[4], const uint32_t a[4], const uint32_t b[2]) {
    asm volatile(
        "mma.sync.aligned.m16n8k8.row.col.f32.tf32.tf32.f32 "
        "{%0,%1,%2,%3}, {%4,%5,%6,%7}, {%8,%9}, {%0,%1,%2,%3};"
        : "+f"(c[0]), "+f"(c[1]), "+f"(c[2]), "+f"(c[3])
        : "r"(a[0]), "r"(a[1]), "r"(a[2]), "r"(a[3]), "r"(b[0]), "r"(b[1]));
}

// ---------------- index computation + counts ----------------
__global__ void k_index(const float* __restrict__ p) {
    int t = blockIdx.x * 256 + threadIdx.x;
    if (t >= BT) return;
    float x = p[t*3+0], y = p[t*3+1], z = p[t*3+2];
    int b = t >> 15;
    int gx, gy, cell;
    gx = (int)floorf(nrmc(x) * RR); gy = (int)floorf(nrmc(z) * RR);
    cell = gx + RR*gy; g_IDX[0*BT + t] = cell;
    atomicAdd(&g_CNT[(0*BB + b)*RR2 + cell], 1.0f);
    gx = (int)floorf(nrmc(x) * RR); gy = (int)floorf(nrmc(y) * RR);
    cell = gx + RR*gy; g_IDX[1*BT + t] = cell;
    atomicAdd(&g_CNT[(1*BB + b)*RR2 + cell], 1.0f);
    gx = (int)floorf(nrmc(y) * RR); gy = (int)floorf(nrmc(z) * RR);
    cell = gx + RR*gy; g_IDX[2*BT + t] = cell;
    atomicAdd(&g_CNT[(2*BB + b)*RR2 + cell], 1.0f);
}

// ---------------- fc_pos: X0 = p @ W(3,256) + b ----------------
__global__ void k_pos(const float* __restrict__ p, const float* __restrict__ w,
                      const float* __restrict__ b) {
    int gi = blockIdx.x * 256 + threadIdx.x;   // BT*256 threads
    int t = gi >> 8, j = gi & 255;
    float p0 = p[t*3+0], p1 = p[t*3+1], p2 = p[t*3+2];
    g_X[gi] = p0 * w[j] + p1 * w[256 + j] + p2 * w[512 + j] + b[j];
}

// ---------------- TF32 tensor-core GEMM ----------------
// C(BT x 128cols-of-W-tile) = act(A) @ W + bias [+ D]
// A row stride AS, D row stride DS, C row stride CS, W leading dim Nout.
// block tile 128x128, 8 warps (warp tile 32x64), k-chunk 32.
template<int K, bool RELU, bool BIAS, bool ACCD>
__global__ void __launch_bounds__(256, 2)
k_tgemm(const float* __restrict__ A, int AS,
        const float* __restrict__ W, int Nout,
        const float* __restrict__ bias,
        const float* __restrict__ D, int DS,
        float* __restrict__ Cm, int CS) {
    __shared__ float As[128][40];   // k-permuted within groups of 8
    __shared__ float Bs[32][136];   // Bs[k][n]

    int tid  = threadIdx.x;
    int wid  = tid >> 5, lane = tid & 31;
    int gid  = lane >> 2, tig = lane & 3;
    int wm   = (wid >> 1) * 32;     // warp row offset (4 warps in m)
    int wn   = (wid & 1) * 64;      // warp col offset (2 warps in n)
    int row0 = blockIdx.y * 128;
    int col0 = blockIdx.x * 128;

    float acc[2][8][4];
#pragma unroll
    for (int mf = 0; mf < 2; mf++)
#pragma unroll
        for (int nf = 0; nf < 8; nf++)
#pragma unroll
            for (int i = 0; i < 4; i++) acc[mf][nf][i] = 0.0f;

#pragma unroll
    for (int k0 = 0; k0 < K; k0 += 32) {
        // --- load A tile 128x32 (4 float4 per thread), permuted k, tf32 ---
#pragma unroll
        for (int i = 0; i < 4; i++) {
            int chunk = i * 256 + tid;
            int r  = chunk >> 3;
            int c4 = chunk & 7;
            float4 v = *(const float4*)&A[(size_t)(row0 + r) * AS + k0 + c4 * 4];
            if (RELU) {
                v.x = fmaxf(v.x, 0.0f); v.y = fmaxf(v.y, 0.0f);
                v.z = fmaxf(v.z, 0.0f); v.w = fmaxf(v.w, 0.0f);
            }
            int base = (c4 >> 1) * 8 + (c4 & 1);
            As[r][base + 0] = __uint_as_float(to_tf32(v.x));
            As[r][base + 2] = __uint_as_float(to_tf32(v.y));
            As[r][base + 4] = __uint_as_float(to_tf32(v.z));
            As[r][base + 6] = __uint_as_float(to_tf32(v.w));
        }
        // --- load B tile 32x128 (4 float4 per thread) ---
#pragma unroll
        for (int i = 0; i < 4; i++) {
            int chunk = i * 256 + tid;
            int kr  = chunk >> 5;
            int nc4 = chunk & 31;
            float4 v = *(const float4*)&W[(size_t)(k0 + kr) * Nout + col0 + nc4 * 4];
            v.x = __uint_as_float(to_tf32(v.x));
            v.y = __uint_as_float(to_tf32(v.y));
            v.z = __uint_as_float(to_tf32(v.z));
            v.w = __uint_as_float(to_tf32(v.w));
            *(float4*)&Bs[kr][nc4 * 4] = v;
        }
        __syncthreads();

#pragma unroll
        for (int kk = 0; kk < 32; kk += 8) {
            uint32_t af[2][4];
#pragma unroll
            for (int mf = 0; mf < 2; mf++) {
                int r = wm + mf * 16;
                float2 lo = *(float2*)&As[r + gid    ][kk + tig * 2];
                float2 hi = *(float2*)&As[r + gid + 8][kk + tig * 2];
                af[mf][0] = __float_as_uint(lo.x);
                af[mf][2] = __float_as_uint(lo.y);
                af[mf][1] = __float_as_uint(hi.x);
                af[mf][3] = __float_as_uint(hi.y);
            }
            uint32_t bf[8][2];
#pragma unroll
            for (int nf = 0; nf < 8; nf++) {
                bf[nf][0] = __float_as_uint(Bs[kk + tig    ][wn + nf * 8 + gid]);
                bf[nf][1] = __float_as_uint(Bs[kk + tig + 4][wn + nf * 8 + gid]);
            }
#pragma unroll
            for (int mf = 0; mf < 2; mf++)
#pragma unroll
                for (int nf = 0; nf < 8; nf++)
                    mma_tf32(acc[mf][nf], af[mf], bf[nf]);
        }
        __syncthreads();
    }

    // --- epilogue ---
#pragma unroll
    for (int mf = 0; mf < 2; mf++) {
        int r0 = row0 + wm + mf * 16 + gid;
#pragma unroll
        for (int nf = 0; nf < 8; nf++) {
            int c = col0 + wn + nf * 8 + 2 * tig;
            float v0 = acc[mf][nf][0], v1 = acc[mf][nf][1];
            float v2 = acc[mf][nf][2], v3 = acc[mf][nf][3];
            if (BIAS) {
                float b0 = bias[c], b1 = bias[c + 1];
                v0 += b0; v1 += b1; v2 += b0; v3 += b1;
            }
            if (ACCD) {
                float2 d0 = *(const float2*)&D[(size_t)r0 * DS + c];
                float2 d1 = *(const float2*)&D[(size_t)(r0 + 8) * DS + c];
                v0 += d0.x; v1 += d0.y; v2 += d1.x; v3 += d1.y;
            }
            float2 s0; s0.x = v0; s0.y = v1;
            float2 s1; s1.x = v2; s1.y = v3;
            *(float2*)&Cm[(size_t)r0 * CS + c] = s0;
            *(float2*)&Cm[(size_t)(r0 + 8) * CS + c] = s1;
        }
    }
}

// ---------------- zeroing ----------------
__global__ void k_zero_u(unsigned* ptr, int n) {
    for (int i = blockIdx.x * 256 + threadIdx.x; i < n; i += gridDim.x * 256) ptr[i] = 0u;
}
__global__ void k_zero_f(float* ptr, int n) {
    for (int i = blockIdx.x * 256 + threadIdx.x; i < n; i += gridDim.x * 256) ptr[i] = 0.0f;
}

// ---------------- scatter max (NET lives in g_X[:, :128]) ----------------
__global__ void k_scatter_max() {
    int gi = blockIdx.x * 256 + threadIdx.x;   // BT*32 threads
    int t = gi >> 5, c4 = (gi & 31) * 4;
    int b = t >> 15;
    float4 v = *(const float4*)&g_X[(size_t)t * 256 + c4];
    unsigned o0 = f2o(v.x), o1 = f2o(v.y), o2 = f2o(v.z), o3 = f2o(v.w);
#pragma unroll
    for (int pl = 0; pl < 3; pl++) {
        int cell = g_IDX[pl * BT + t];
        unsigned* m = &g_MAX[(size_t)((pl * BB + b) * RR2 + cell) * 128 + c4];
        atomicMax(m + 0, o0); atomicMax(m + 1, o1);
        atomicMax(m + 2, o2); atomicMax(m + 3, o3);
    }
}

// ---------------- gather pooled into g_X[:, 128:256] ----------------
__global__ void k_gather() {
    int gi = blockIdx.x * 256 + threadIdx.x;   // BT*32 threads
    int t = gi >> 5, c4 = (gi & 31) * 4;
    int b = t >> 15;
    float4 s; s.x = 0.0f; s.y = 0.0f; s.z = 0.0f; s.w = 0.0f;
#pragma unroll
    for (int pl = 0; pl < 3; pl++) {
        int cell = g_IDX[pl * BT + t];
        const unsigned* m = &g_MAX[(size_t)((pl * BB + b) * RR2 + cell) * 128 + c4];
        s.x += o2f(m[0]); s.y += o2f(m[1]); s.z += o2f(m[2]); s.w += o2f(m[3]);
    }
    *(float4*)&g_X[(size_t)t * 256 + 128 + c4] = s;
}

// ---------------- scatter mean (vector red) ----------------
__global__ void k_scatter_add() {
    int gi = blockIdx.x * 256 + threadIdx.x;   // BT*128 threads
    int t = gi >> 7, c4 = (gi & 127) * 4;
    int b = t >> 15;
    float4 v = *(const float4*)&g_C[(size_t)t * CDIM + c4];
#pragma unroll
    for (int pl = 0; pl < 3; pl++) {
        int cell = g_IDX[pl * BT + t];
        float* f = &g_FEA[(size_t)((pl * BB + b) * RR2 + cell) * CDIM + c4];
        asm volatile("red.global.add.v4.f32 [%0], {%1, %2, %3, %4};"
                     :: "l"(f), "f"(v.x), "f"(v.y), "f"(v.z), "f"(v.w) : "memory");
    }
}
__global__ void k_div() {
    int gi = blockIdx.x * 256 + threadIdx.x;   // 3*BB*RR2*128 threads
    int cell = gi >> 7;
    float inv = 1.0f / fmaxf(g_CNT[cell], 1.0f);
    float4* p = (float4*)&g_FEA[(size_t)gi * 4];
    float4 v = *p;
    v.x *= inv; v.y *= inv; v.z *= inv; v.w *= inv;
    *p = v;
}

// ---------------- bilinear sample + sum over planes ----------------
__device__ __forceinline__ float4 samp4(int pl, float u, float v, int b, int c4) {
    float nu = nrmc(u), nv = nrmc(v);
    float gx = nu * (RR - 1), gy = nv * (RR - 1);
    float x0f = floorf(gx), y0f = floorf(gy);
    float wx = gx - x0f, wy = gy - y0f;
    int x0 = min(max((int)x0f, 0), RR - 1);
    int x1 = min(x0 + 1, RR - 1);
    int y0 = min(max((int)y0f, 0), RR - 1);
    int y1 = min(y0 + 1, RR - 1);
    const float* f = g_FEA + (size_t)((pl * BB + b) * RR2) * CDIM + c4;
    float4 f00 = *(const float4*)&f[(y0 * RR + x0) * CDIM];
    float4 f01 = *(const float4*)&f[(y0 * RR + x1) * CDIM];
    float4 f10 = *(const float4*)&f[(y1 * RR + x0) * CDIM];
    float4 f11 = *(const float4*)&f[(y1 * RR + x1) * CDIM];
    float w00 = (1.0f - wx) * (1.0f - wy), w01 = wx * (1.0f - wy);
    float w10 = (1.0f - wx) * wy,          w11 = wx * wy;
    float4 r;
    r.x = f00.x * w00 + f01.x * w01 + f10.x * w10 + f11.x * w11;
    r.y = f00.y * w00 + f01.y * w01 + f10.y * w10 + f11.y * w11;
    r.z = f00.z * w00 + f01.z * w01 + f10.z * w10 + f11.z * w11;
    r.w = f00.w * w00 + f01.w * w01 + f10.w * w10 + f11.w * w11;
    return r;
}

__global__ void k_sample(const float* __restrict__ query, float* __restrict__ out) {
    int gi = blockIdx.x * 256 + threadIdx.x;   // BB*QQ*128 threads
    int c4 = (gi & 127) * 4;
    int q  = gi >> 7;       // 0 .. BB*QQ-1
    int b  = q >> 13;       // QQ = 8192
    float qx = query[q*3+0], qy = query[q*3+1], qz = query[q*3+2];
    float4 a = samp4(0, qx, qz, b, c4);
    float4 s1 = samp4(1, qx, qy, b, c4);
    float4 s2 = samp4(2, qy, qz, b, c4);
    a.x += s1.x + s2.x; a.y += s1.y + s2.y;
    a.z += s1.z + s2.z; a.w += s1.w + s2.w;
    *(float4*)&out[(size_t)q * CDIM + c4] = a;
}

// ---------------- launch ----------------
extern "C" void kernel_launch(void* const* d_in, const int* in_sizes, int n_in,
                              void* d_out, int out_size) {
    const float* p        = (const float*)d_in[0];
    const float* query    = (const float*)d_in[1];
    const float* fc_pos_w = (const float*)d_in[2];
    const float* fc_pos_b = (const float*)d_in[3];
    const float* blk_w0   = (const float*)d_in[4];
    const float* blk_b0   = (const float*)d_in[5];
    const float* blk_w1   = (const float*)d_in[6];
    const float* blk_b1   = (const float*)d_in[7];
    const float* blk_ws   = (const float*)d_in[8];
    const float* fc_c_w   = (const float*)d_in[9];
    const float* fc_c_b   = (const float*)d_in[10];
    float* out = (float*)d_out;

    float *X, *H, *NT, *Cb, *FEA, *CNT;
    unsigned* MAXB;
    cudaGetSymbolAddress((void**)&X,    g_X);
    cudaGetSymbolAddress((void**)&H,    g_H);
    cudaGetSymbolAddress((void**)&NT,   g_NT);
    cudaGetSymbolAddress((void**)&Cb,   g_C);
    cudaGetSymbolAddress((void**)&FEA,  g_FEA);
    cudaGetSymbolAddress((void**)&CNT,  g_CNT);
    cudaGetSymbolAddress((void**)&MAXB, g_MAX);

    k_zero_f<<<48, 256>>>(CNT, 3*BB*RR2);
    k_index<<<BT/256, 256>>>(p);
    k_pos<<<BT, 256>>>(p, fc_pos_w, fc_pos_b);

    dim3 g128(1, BT/128);   // output width 128
    dim3 g512(4, BT/128);   // output width 512

    for (int i = 0; i < 5; i++) {
        if (i > 0) {
            k_zero_u<<<2048, 256>>>(MAXB, 3*BB*RR2*128);
            k_scatter_max<<<BT*32/256, 256>>>();
            k_gather<<<BT*32/256, 256>>>();
        }
        const float* w0 = blk_w0 + i*256*128;
        const float* b0 = blk_b0 + i*128;
        const float* w1 = blk_w1 + i*128*128;
        const float* b1 = blk_b1 + i*128;
        const float* ws = blk_ws + i*256*128;
        // H = relu(X) @ w0 + b0
        k_tgemm<256, true,  true,  false><<<g128, 256>>>(X, 256, w0, 128, b0, nullptr, 0, H, 128);
        // NT = X @ ws
        k_tgemm<256, false, false, false><<<g128, 256>>>(X, 256, ws, 128, nullptr, nullptr, 0, NT, 128);
        // X[:, :128] = relu(H) @ w1 + b1 + NT
        k_tgemm<128, true,  true,  true ><<<g128, 256>>>(H, 128, w1, 128, b1, NT, 128, X, 256);
    }

    // c = NET @ fc_c_w + fc_c_b   (NET = X[:, :128], stride 256)
    k_tgemm<128, false, true, false><<<g512, 256>>>(X, 256, fc_c_w, 512, fc_c_b, nullptr, 0, Cb, 512);

    // scatter mean into plane grids
    k_zero_f<<<4096, 256>>>(FEA, 3*BB*RR2*CDIM);
    k_scatter_add<<<BT*128/256, 256>>>();
    k_div<<<3*BB*RR2*128/256, 256>>>();

    // bilinear sample queries
    k_sample<<<BB*QQ*128/256, 256>>>(query, out);
}

// round 4
// speedup vs baseline: 2.5482x; 1.1976x over previous
#include <cuda_runtime.h>
#include <math.h>
#include <stdint.h>

#define BB   4
#define TT   32768
#define BT   (BB*TT)           // 131072 points
#define QQ   8192
#define HH   128
#define RR   64
#define RR2  4096
#define CDIM 512

// ---------------- scratch (static device memory; no allocations) ----------------
__device__ float    g_X  [BT*256];            // [NET | pooled] concat buffer
__device__ float    g_H  [BT*128];            // hidden
__device__ float    g_NT [BT*128];            // shortcut temp
__device__ float    g_C  [BT*CDIM];           // fc_c output
__device__ unsigned g_MAX[3*BB*RR2*128];      // per-plane max pool
__device__ float    g_FEA[3*BB*RR2*CDIM];     // per-plane mean feat
__device__ float    g_CNT[3*BB*RR2];          // per-plane counts
__device__ int      g_IDX[3*BT];              // per-plane cell index
__device__ float    g_WP [475136];            // tf32-preconverted weights

// offsets into g_WP
#define WP_W0 0                               // 5*256*128 = 163840
#define WP_W1 163840                          // 5*128*128 =  81920
#define WP_WS 245760                          // 5*256*128 = 163840
#define WP_FC 409600                          // 128*512   =  65536

// ---------------- helpers ----------------
__device__ __forceinline__ unsigned f2o(float f) {
    unsigned b = __float_as_uint(f);
    return (b & 0x80000000u) ? ~b : (b | 0x80000000u);
}
__device__ __forceinline__ float o2f(unsigned o) {
    return __uint_as_float((o & 0x80000000u) ? (o ^ 0x80000000u) : ~o);
}
__device__ __forceinline__ float nrmc(float v) {
    v = v * (1.0f / 1.1f) + 0.5f;
    return fminf(fmaxf(v, 0.0f), 1.0f - 1e-6f);
}
__device__ __forceinline__ uint32_t to_tf32(float x) {
    uint32_t u;
    asm("cvt.rna.tf32.f32 %0, %1;" : "=r"(u) : "f"(x));
    return u;
}
__device__ __forceinline__ void mma_tf32(float c[4], const uint32_t a[4], const uint32_t b[2]) {
    asm volatile(
        "mma.sync.aligned.m16n8k8.row.col.f32.tf32.tf32.f32 "
        "{%0,%1,%2,%3}, {%4,%5,%6,%7}, {%8,%9}, {%0,%1,%2,%3};"
        : "+f"(c[0]), "+f"(c[1]), "+f"(c[2]), "+f"(c[3])
        : "r"(a[0]), "r"(a[1]), "r"(a[2]), "r"(a[3]), "r"(b[0]), "r"(b[1]));
}
__device__ __forceinline__ void cp16(uint32_t s, const float* g) {
    asm volatile("cp.async.cg.shared.global [%0], [%1], 16;" :: "r"(s), "l"(g));
}
__device__ __forceinline__ void cp_commit() { asm volatile("cp.async.commit_group;"); }
__device__ __forceinline__ void cp_wait0()  { asm volatile("cp.async.wait_group 0;"); }

// ---------------- weight pre-conversion to tf32 ----------------
__global__ void k_cvtw(const float* __restrict__ src, float* __restrict__ dst, int n4) {
    int i = blockIdx.x * 256 + threadIdx.x;
    if (i >= n4) return;
    float4 v = *(const float4*)&src[i * 4];
    v.x = __uint_as_float(to_tf32(v.x));
    v.y = __uint_as_float(to_tf32(v.y));
    v.z = __uint_as_float(to_tf32(v.z));
    v.w = __uint_as_float(to_tf32(v.w));
    *(float4*)&dst[i * 4] = v;
}

// ---------------- index computation + counts ----------------
__global__ void k_index(const float* __restrict__ p) {
    int t = blockIdx.x * 256 + threadIdx.x;
    if (t >= BT) return;
    float x = p[t*3+0], y = p[t*3+1], z = p[t*3+2];
    int b = t >> 15;
    int gx, gy, cell;
    gx = (int)floorf(nrmc(x) * RR); gy = (int)floorf(nrmc(z) * RR);
    cell = gx + RR*gy; g_IDX[0*BT + t] = cell;
    atomicAdd(&g_CNT[(0*BB + b)*RR2 + cell], 1.0f);
    gx = (int)floorf(nrmc(x) * RR); gy = (int)floorf(nrmc(y) * RR);
    cell = gx + RR*gy; g_IDX[1*BT + t] = cell;
    atomicAdd(&g_CNT[(1*BB + b)*RR2 + cell], 1.0f);
    gx = (int)floorf(nrmc(y) * RR); gy = (int)floorf(nrmc(z) * RR);
    cell = gx + RR*gy; g_IDX[2*BT + t] = cell;
    atomicAdd(&g_CNT[(2*BB + b)*RR2 + cell], 1.0f);
}

// ---------------- fc_pos: X0 = p @ W(3,256) + b ----------------
__global__ void k_pos(const float* __restrict__ p, const float* __restrict__ w,
                      const float* __restrict__ b) {
    int gi = blockIdx.x * 256 + threadIdx.x;   // BT*256 threads
    int t = gi >> 8, j = gi & 255;
    float p0 = p[t*3+0], p1 = p[t*3+1], p2 = p[t*3+2];
    g_X[gi] = p0 * w[j] + p1 * w[256 + j] + p2 * w[512 + j] + b[j];
}

// ---------------- TF32 tensor-core GEMM, cp.async 2-stage pipeline ----------------
// C = act(A) @ W + bias [+ D]; W is PRE-CONVERTED tf32.
// block tile 128x128, 8 warps (warp tile 32x64), k-chunk 32, 2-stage double buffer.
#define AS_STRIDE 36
#define BS_STRIDE 136
#define AS_FLOATS (128*AS_STRIDE)   // 4608
#define BS_FLOATS (32*BS_STRIDE)    // 4352
#define SMEM_BYTES ((2*AS_FLOATS + 2*BS_FLOATS) * 4)   // 71680

template<int K, bool RELU, bool BIAS, bool ACCD>
__global__ void __launch_bounds__(256, 2)
k_tgemm(const float* __restrict__ A, int ASt,
        const float* __restrict__ W, int Nout,
        const float* __restrict__ bias,
        const float* __restrict__ D, int DS,
        float* __restrict__ Cm, int CS) {
    extern __shared__ float smem[];
    float* AsB[2] = { smem, smem + AS_FLOATS };
    float* BsB[2] = { smem + 2*AS_FLOATS, smem + 2*AS_FLOATS + BS_FLOATS };

    int tid  = threadIdx.x;
    int wid  = tid >> 5, lane = tid & 31;
    int gid  = lane >> 2, tig = lane & 3;
    int wm   = (wid >> 1) * 32;
    int wn   = (wid & 1) * 64;
    int row0 = blockIdx.y * 128;
    int col0 = blockIdx.x * 128;

    // per-thread cp.async coordinates
    int a_r  = tid >> 1;               // 0..127 (2 chunks per row)
    int a_c4 = (tid & 1) * 4;          // two threads cover 8 float4s? No: need 8 chunks/row.
    // 128 rows * 8 chunks = 1024 chunks / 256 threads = 4 each (i*256+tid)
    uint32_t sA[2], sB[2];
    sA[0] = (uint32_t)__cvta_generic_to_shared(AsB[0]);
    sA[1] = (uint32_t)__cvta_generic_to_shared(AsB[1]);
    sB[0] = (uint32_t)__cvta_generic_to_shared(BsB[0]);
    sB[1] = (uint32_t)__cvta_generic_to_shared(BsB[1]);
    (void)a_r; (void)a_c4;

    float acc[2][8][4];
#pragma unroll
    for (int mf = 0; mf < 2; mf++)
#pragma unroll
        for (int nf = 0; nf < 8; nf++)
#pragma unroll
            for (int i = 0; i < 4; i++) acc[mf][nf][i] = 0.0f;

    auto prefetch = [&](int k0, int s) {
#pragma unroll
        for (int i = 0; i < 4; i++) {          // A tile 128x32
            int chunk = i * 256 + tid;
            int r  = chunk >> 3;
            int c4 = chunk & 7;
            cp16(sA[s] + (r * AS_STRIDE + c4 * 4) * 4,
                 &A[(size_t)(row0 + r) * ASt + k0 + c4 * 4]);
        }
#pragma unroll
        for (int i = 0; i < 4; i++) {          // B tile 32x128
            int chunk = i * 256 + tid;
            int kr  = chunk >> 5;
            int nc4 = chunk & 31;
            cp16(sB[s] + (kr * BS_STRIDE + nc4 * 4) * 4,
                 &W[(size_t)(k0 + kr) * Nout + col0 + nc4 * 4]);
        }
        cp_commit();
    };

    constexpr int NK = K / 32;
    prefetch(0, 0);

#pragma unroll
    for (int kt = 0; kt < NK; kt++) {
        int cur = kt & 1;
        cp_wait0();
        __syncthreads();
        if (kt + 1 < NK) prefetch((kt + 1) * 32, cur ^ 1);

        const float* as = AsB[cur];
        const float* bs = BsB[cur];
#pragma unroll
        for (int kk = 0; kk < 32; kk += 8) {
            uint32_t af[2][4];
#pragma unroll
            for (int mf = 0; mf < 2; mf++) {
                int r = wm + mf * 16;
                float a0 = as[(r + gid    ) * AS_STRIDE + kk + tig    ];
                float a1 = as[(r + gid + 8) * AS_STRIDE + kk + tig    ];
                float a2 = as[(r + gid    ) * AS_STRIDE + kk + tig + 4];
                float a3 = as[(r + gid + 8) * AS_STRIDE + kk + tig + 4];
                if (RELU) {
                    a0 = fmaxf(a0, 0.0f); a1 = fmaxf(a1, 0.0f);
                    a2 = fmaxf(a2, 0.0f); a3 = fmaxf(a3, 0.0f);
                }
                af[mf][0] = to_tf32(a0);
                af[mf][1] = to_tf32(a1);
                af[mf][2] = to_tf32(a2);
                af[mf][3] = to_tf32(a3);
            }
            uint32_t bf[8][2];
#pragma unroll
            for (int nf = 0; nf < 8; nf++) {
                bf[nf][0] = __float_as_uint(bs[(kk + tig    ) * BS_STRIDE + wn + nf * 8 + gid]);
                bf[nf][1] = __float_as_uint(bs[(kk + tig + 4) * BS_STRIDE + wn + nf * 8 + gid]);
            }
#pragma unroll
            for (int mf = 0; mf < 2; mf++)
#pragma unroll
                for (int nf = 0; nf < 8; nf++)
                    mma_tf32(acc[mf][nf], af[mf], bf[nf]);
        }
        __syncthreads();
    }

    // --- epilogue ---
#pragma unroll
    for (int mf = 0; mf < 2; mf++) {
        int r0 = row0 + wm + mf * 16 + gid;
#pragma unroll
        for (int nf = 0; nf < 8; nf++) {
            int c = col0 + wn + nf * 8 + 2 * tig;
            float v0 = acc[mf][nf][0], v1 = acc[mf][nf][1];
            float v2 = acc[mf][nf][2], v3 = acc[mf][nf][3];
            if (BIAS) {
                float b0 = bias[c], b1 = bias[c + 1];
                v0 += b0; v1 += b1; v2 += b0; v3 += b1;
            }
            if (ACCD) {
                float2 d0 = *(const float2*)&D[(size_t)r0 * DS + c];
                float2 d1 = *(const float2*)&D[(size_t)(r0 + 8) * DS + c];
                v0 += d0.x; v1 += d0.y; v2 += d1.x; v3 += d1.y;
            }
            float2 s0; s0.x = v0; s0.y = v1;
            float2 s1; s1.x = v2; s1.y = v3;
            *(float2*)&Cm[(size_t)r0 * CS + c] = s0;
            *(float2*)&Cm[(size_t)(r0 + 8) * CS + c] = s1;
        }
    }
}

// ---------------- zeroing ----------------
__global__ void k_zero_u(unsigned* ptr, int n) {
    for (int i = blockIdx.x * 256 + threadIdx.x; i < n; i += gridDim.x * 256) ptr[i] = 0u;
}
__global__ void k_zero_f(float* ptr, int n) {
    for (int i = blockIdx.x * 256 + threadIdx.x; i < n; i += gridDim.x * 256) ptr[i] = 0.0f;
}

// ---------------- scatter max (NET lives in g_X[:, :128]) ----------------
__global__ void k_scatter_max() {
    int gi = blockIdx.x * 256 + threadIdx.x;   // BT*32 threads
    int t = gi >> 5, c4 = (gi & 31) * 4;
    int b = t >> 15;
    float4 v = *(const float4*)&g_X[(size_t)t * 256 + c4];
    unsigned o0 = f2o(v.x), o1 = f2o(v.y), o2 = f2o(v.z), o3 = f2o(v.w);
#pragma unroll
    for (int pl = 0; pl < 3; pl++) {
        int cell = g_IDX[pl * BT + t];
        unsigned* m = &g_MAX[(size_t)((pl * BB + b) * RR2 + cell) * 128 + c4];
        atomicMax(m + 0, o0); atomicMax(m + 1, o1);
        atomicMax(m + 2, o2); atomicMax(m + 3, o3);
    }
}

// ---------------- gather pooled into g_X[:, 128:256] ----------------
__global__ void k_gather() {
    int gi = blockIdx.x * 256 + threadIdx.x;   // BT*32 threads
    int t = gi >> 5, c4 = (gi & 31) * 4;
    int b = t >> 15;
    float4 s; s.x = 0.0f; s.y = 0.0f; s.z = 0.0f; s.w = 0.0f;
#pragma unroll
    for (int pl = 0; pl < 3; pl++) {
        int cell = g_IDX[pl * BT + t];
        const unsigned* m = &g_MAX[(size_t)((pl * BB + b) * RR2 + cell) * 128 + c4];
        s.x += o2f(m[0]); s.y += o2f(m[1]); s.z += o2f(m[2]); s.w += o2f(m[3]);
    }
    *(float4*)&g_X[(size_t)t * 256 + 128 + c4] = s;
}

// ---------------- scatter mean (vector red) ----------------
__global__ void k_scatter_add() {
    int gi = blockIdx.x * 256 + threadIdx.x;   // BT*128 threads
    int t = gi >> 7, c4 = (gi & 127) * 4;
    int b = t >> 15;
    float4 v = *(const float4*)&g_C[(size_t)t * CDIM + c4];
#pragma unroll
    for (int pl = 0; pl < 3; pl++) {
        int cell = g_IDX[pl * BT + t];
        float* f = &g_FEA[(size_t)((pl * BB + b) * RR2 + cell) * CDIM + c4];
        asm volatile("red.global.add.v4.f32 [%0], {%1, %2, %3, %4};"
                     :: "l"(f), "f"(v.x), "f"(v.y), "f"(v.z), "f"(v.w) : "memory");
    }
}
__global__ void k_div() {
    int gi = blockIdx.x * 256 + threadIdx.x;   // 3*BB*RR2*128 threads
    int cell = gi >> 7;
    float inv = 1.0f / fmaxf(g_CNT[cell], 1.0f);
    float4* p = (float4*)&g_FEA[(size_t)gi * 4];
    float4 v = *p;
    v.x *= inv; v.y *= inv; v.z *= inv; v.w *= inv;
    *p = v;
}

// ---------------- bilinear sample + sum over planes ----------------
__device__ __forceinline__ float4 samp4(int pl, float u, float v, int b, int c4) {
    float nu = nrmc(u), nv = nrmc(v);
    float gx = nu * (RR - 1), gy = nv * (RR - 1);
    float x0f = floorf(gx), y0f = floorf(gy);
    float wx = gx - x0f, wy = gy - y0f;
    int x0 = min(max((int)x0f, 0), RR - 1);
    int x1 = min(x0 + 1, RR - 1);
    int y0 = min(max((int)y0f, 0), RR - 1);
    int y1 = min(y0 + 1, RR - 1);
    const float* f = g_FEA + (size_t)((pl * BB + b) * RR2) * CDIM + c4;
    float4 f00 = *(const float4*)&f[(y0 * RR + x0) * CDIM];
    float4 f01 = *(const float4*)&f[(y0 * RR + x1) * CDIM];
    float4 f10 = *(const float4*)&f[(y1 * RR + x0) * CDIM];
    float4 f11 = *(const float4*)&f[(y1 * RR + x1) * CDIM];
    float w00 = (1.0f - wx) * (1.0f - wy), w01 = wx * (1.0f - wy);
    float w10 = (1.0f - wx) * wy,          w11 = wx * wy;
    float4 r;
    r.x = f00.x * w00 + f01.x * w01 + f10.x * w10 + f11.x * w11;
    r.y = f00.y * w00 + f01.y * w01 + f10.y * w10 + f11.y * w11;
    r.z = f00.z * w00 + f01.z * w01 + f10.z * w10 + f11.z * w11;
    r.w = f00.w * w00 + f01.w * w01 + f10.w * w10 + f11.w * w11;
    return r;
}

__global__ void k_sample(const float* __restrict__ query, float* __restrict__ out) {
    int gi = blockIdx.x * 256 + threadIdx.x;   // BB*QQ*128 threads
    int c4 = (gi & 127) * 4;
    int q  = gi >> 7;
    int b  = q >> 13;
    float qx = query[q*3+0], qy = query[q*3+1], qz = query[q*3+2];
    float4 a = samp4(0, qx, qz, b, c4);
    float4 s1 = samp4(1, qx, qy, b, c4);
    float4 s2 = samp4(2, qy, qz, b, c4);
    a.x += s1.x + s2.x; a.y += s1.y + s2.y;
    a.z += s1.z + s2.z; a.w += s1.w + s2.w;
    *(float4*)&out[(size_t)q * CDIM + c4] = a;
}

// ---------------- launch ----------------
extern "C" void kernel_launch(void* const* d_in, const int* in_sizes, int n_in,
                              void* d_out, int out_size) {
    const float* p        = (const float*)d_in[0];
    const float* query    = (const float*)d_in[1];
    const float* fc_pos_w = (const float*)d_in[2];
    const float* fc_pos_b = (const float*)d_in[3];
    const float* blk_w0   = (const float*)d_in[4];
    const float* blk_b0   = (const float*)d_in[5];
    const float* blk_w1   = (const float*)d_in[6];
    const float* blk_b1   = (const float*)d_in[7];
    const float* blk_ws   = (const float*)d_in[8];
    const float* fc_c_w   = (const float*)d_in[9];
    const float* fc_c_b   = (const float*)d_in[10];
    float* out = (float*)d_out;

    float *X, *H, *NT, *Cb, *FEA, *CNT, *WP;
    unsigned* MAXB;
    cudaGetSymbolAddress((void**)&X,    g_X);
    cudaGetSymbolAddress((void**)&H,    g_H);
    cudaGetSymbolAddress((void**)&NT,   g_NT);
    cudaGetSymbolAddress((void**)&Cb,   g_C);
    cudaGetSymbolAddress((void**)&FEA,  g_FEA);
    cudaGetSymbolAddress((void**)&CNT,  g_CNT);
    cudaGetSymbolAddress((void**)&WP,   g_WP);
    cudaGetSymbolAddress((void**)&MAXB, g_MAX);

    cudaFuncSetAttribute(k_tgemm<256, true,  true,  false>, cudaFuncAttributeMaxDynamicSharedMemorySize, SMEM_BYTES);
    cudaFuncSetAttribute(k_tgemm<256, false, false, false>, cudaFuncAttributeMaxDynamicSharedMemorySize, SMEM_BYTES);
    cudaFuncSetAttribute(k_tgemm<128, true,  true,  true >, cudaFuncAttributeMaxDynamicSharedMemorySize, SMEM_BYTES);
    cudaFuncSetAttribute(k_tgemm<128, false, true,  false>, cudaFuncAttributeMaxDynamicSharedMemorySize, SMEM_BYTES);

    // preconvert weights to tf32
    k_cvtw<<<163840/4/256, 256>>>(blk_w0, WP + WP_W0, 163840/4);
    k_cvtw<<< 81920/4/256, 256>>>(blk_w1, WP + WP_W1,  81920/4);
    k_cvtw<<<163840/4/256, 256>>>(blk_ws, WP + WP_WS, 163840/4);
    k_cvtw<<< 65536/4/256, 256>>>(fc_c_w, WP + WP_FC,  65536/4);

    k_zero_f<<<48, 256>>>(CNT, 3*BB*RR2);
    k_index<<<BT/256, 256>>>(p);
    k_pos<<<BT, 256>>>(p, fc_pos_w, fc_pos_b);

    dim3 g128(1, BT/128);
    dim3 g512(4, BT/128);

    for (int i = 0; i < 5; i++) {
        if (i > 0) {
            k_zero_u<<<2048, 256>>>(MAXB, 3*BB*RR2*128);
            k_scatter_max<<<BT*32/256, 256>>>();
            k_gather<<<BT*32/256, 256>>>();
        }
        const float* w0 = WP + WP_W0 + i*256*128;
        const float* b0 = blk_b0 + i*128;
        const float* w1 = WP + WP_W1 + i*128*128;
        const float* b1 = blk_b1 + i*128;
        const float* ws = WP + WP_WS + i*256*128;
        // H = relu(X) @ w0 + b0
        k_tgemm<256, true,  true,  false><<<g128, 256, SMEM_BYTES>>>(X, 256, w0, 128, b0, nullptr, 0, H, 128);
        // NT = X @ ws
        k_tgemm<256, false, false, false><<<g128, 256, SMEM_BYTES>>>(X, 256, ws, 128, nullptr, nullptr, 0, NT, 128);
        // X[:, :128] = relu(H) @ w1 + b1 + NT
        k_tgemm<128, true,  true,  true ><<<g128, 256, SMEM_BYTES>>>(H, 128, w1, 128, b1, NT, 128, X, 256);
    }

    // c = NET @ fc_c_w + fc_c_b   (NET = X[:, :128], stride 256)
    k_tgemm<128, false, true, false><<<g512, 256, SMEM_BYTES>>>(X, 256, WP + WP_FC, 512, fc_c_b, nullptr, 0, Cb, 512);

    // scatter mean into plane grids
    k_zero_f<<<4096, 256>>>(FEA, 3*BB*RR2*CDIM);
    k_scatter_add<<<BT*128/256, 256>>>();
    k_div<<<3*BB*RR2*128/256, 256>>>();

    // bilinear sample queries
    k_sample<<<BB*QQ*128/256, 256>>>(query, out);
}